// round 9
// baseline (speedup 1.0000x reference)
#include <cuda_runtime.h>
#include <cstdint>
#include <math.h>

// Router: probs = softmax(calib(H @ W^T)), top-8.
// Kernel1: mma.sync tf32 (3x split) -> probs only (1.5e-5 norm err, passes).
// Kernel2: for EVERY token, exact sequential-k fp32 recompute of its top-12
//          candidate logits (replicates the reference GEMM's ascending-k
//          accumulation order -> bit-stable ranking), re-ranks top-8, writes
//          weights (gathered MMA probs in exact order) + indices.
// Output packing: d_out = probs[T*64] || topk_w[T*8] || topk_idx(as float)[T*8]

#define TM   128
#define NE   64
#define DD   2048
#define KC   32
#define NCH  (DD / KC)
#define NT   256
#define TOPK 8

#define STAGE_BYTES 49152
#define A_HI 0
#define A_LO 16384
#define B_HI 32768
#define B_LO 40960
#define SM_CAL  (2 * STAGE_BYTES)
#define SM_BIAS (SM_CAL + 256)
#define SMEM_TOTAL (SM_CAL + 512)

// fixup config
#define FT    64          // tokens per fixup block
#define FKT   128         // k tile
#define FNT   256         // fixup threads
#define NCAND 12
#define FSTR  132         // padded row stride (floats) for sA/sW

static __device__ __forceinline__ uint32_t smem_u32(const void* p) {
    uint32_t a;
    asm("{ .reg .u64 t; cvta.to.shared.u64 t, %1; cvt.u32.u64 %0, t; }" : "=r"(a) : "l"(p));
    return a;
}
static __device__ __forceinline__ uint32_t f2tf(float x) {
    uint32_t r; asm("cvt.rna.tf32.f32 %0, %1;" : "=r"(r) : "f"(x)); return r;
}
static __device__ __forceinline__ void split4(float4 v, uint4& h, uint4& l) {
    h.x = f2tf(v.x); l.x = f2tf(v.x - __uint_as_float(h.x));
    h.y = f2tf(v.y); l.y = f2tf(v.y - __uint_as_float(h.y));
    h.z = f2tf(v.z); l.z = f2tf(v.z - __uint_as_float(h.z));
    h.w = f2tf(v.w); l.w = f2tf(v.w - __uint_as_float(h.w));
}
static __device__ __forceinline__ void ldsm4(uint32_t* r, uint32_t addr) {
    asm volatile("ldmatrix.sync.aligned.m8n8.x4.shared.b16 {%0,%1,%2,%3}, [%4];"
        : "=r"(r[0]), "=r"(r[1]), "=r"(r[2]), "=r"(r[3]) : "r"(addr));
}
static __device__ __forceinline__ void mma8(float* c, const uint32_t* a,
                                            uint32_t b0, uint32_t b1) {
    asm volatile("mma.sync.aligned.m16n8k8.row.col.f32.tf32.tf32.f32 "
        "{%0,%1,%2,%3}, {%4,%5,%6,%7}, {%8,%9}, {%0,%1,%2,%3};"
        : "+f"(c[0]), "+f"(c[1]), "+f"(c[2]), "+f"(c[3])
        : "r"(a[0]), "r"(a[1]), "r"(a[2]), "r"(a[3]), "r"(b0), "r"(b1));
}

extern "C" __global__ void __launch_bounds__(NT, 1)
router_mma(const float* __restrict__ A, const float* __restrict__ W,
           const float* __restrict__ cal_s, const float* __restrict__ cal_b,
           float* __restrict__ out_probs)
{
    extern __shared__ __align__(16) char smem[];
    const uint32_t sbase = smem_u32(smem);
    const int tid  = threadIdx.x;
    const int lane = tid & 31;
    const int w    = tid >> 5;
    const int wm   = w >> 1;
    const int wn   = w & 1;
    const int m0   = blockIdx.x * TM;

    float* s_cal  = reinterpret_cast<float*>(smem + SM_CAL);
    float* s_bias = reinterpret_cast<float*>(smem + SM_BIAS);
    if (tid < NE) { s_cal[tid] = cal_s[tid]; s_bias[tid] = cal_b[tid]; }

    const int ra = tid >> 3;
    const int c4 = tid & 7;
    uint32_t offA[4], offB[2];
#pragma unroll
    for (int it = 0; it < 4; ++it) {
        const int t = ra + it * 32;
        offA[it] = (uint32_t)t * 128 + (uint32_t)((c4 ^ (t & 7)) << 4);
    }
#pragma unroll
    for (int it = 0; it < 2; ++it) {
        const int t = ra + it * 32;
        offB[it] = (uint32_t)t * 128 + (uint32_t)((c4 ^ (t & 7)) << 4);
    }
    const float* Ap = A + (size_t)(m0 + ra) * DD + c4 * 4;
    const float* Wp = W + (size_t)ra * DD + c4 * 4;

#pragma unroll
    for (int cc = 0; cc < 2; ++cc) {
        char* st = smem + cc * STAGE_BYTES;
        const int k0 = cc * KC;
#pragma unroll
        for (int it = 0; it < 4; ++it) {
            float4 v = *reinterpret_cast<const float4*>(Ap + (size_t)it * 32 * DD + k0);
            uint4 h, l; split4(v, h, l);
            *reinterpret_cast<uint4*>(st + A_HI + offA[it]) = h;
            *reinterpret_cast<uint4*>(st + A_LO + offA[it]) = l;
        }
#pragma unroll
        for (int it = 0; it < 2; ++it) {
            float4 v = *reinterpret_cast<const float4*>(Wp + (size_t)it * 32 * DD + k0);
            uint4 h, l; split4(v, h, l);
            *reinterpret_cast<uint4*>(st + B_HI + offB[it]) = h;
            *reinterpret_cast<uint4*>(st + B_LO + offB[it]) = l;
        }
    }
    __syncthreads();

    float4 pa[4], pb[2];
    {
        const int k0 = 2 * KC;
#pragma unroll
        for (int it = 0; it < 4; ++it)
            pa[it] = *reinterpret_cast<const float4*>(Ap + (size_t)it * 32 * DD + k0);
#pragma unroll
        for (int it = 0; it < 2; ++it)
            pb[it] = *reinterpret_cast<const float4*>(Wp + (size_t)it * 32 * DD + k0);
    }

    const int arow = wm * 32 + (lane & 15);
    const int acs  = lane >> 4;
    const int ax   = arow & 7;
    const uint32_t abase0 = sbase + A_HI + (uint32_t)arow * 128;
    const int g    = lane >> 3;
    const int brow = wn * 32 + ((g >> 1) << 3) + (lane & 7);
    const int bcs  = g & 1;
    const int bx   = brow & 7;
    const uint32_t bbase0 = sbase + B_HI + (uint32_t)brow * 128;

    float acc[2][4][4];
#pragma unroll
    for (int mt = 0; mt < 2; ++mt)
#pragma unroll
        for (int nt = 0; nt < 4; ++nt)
#pragma unroll
            for (int q = 0; q < 4; ++q) acc[mt][nt][q] = 0.f;

#pragma unroll 1
    for (int c = 0; c < NCH; ++c) {
        const uint32_t stoff = (uint32_t)(c & 1) * STAGE_BYTES;
        const uint32_t aS = abase0 + stoff;
        const uint32_t bS = bbase0 + stoff;

#pragma unroll
        for (int s8 = 0; s8 < 4; ++s8) {
            uint32_t ah[8], al[8], bb[8];
            const uint32_t acol = (uint32_t)(((2 * s8 + acs) ^ ax) << 4);
            const uint32_t bcol = (uint32_t)(((2 * s8 + bcs) ^ bx) << 4);

            ldsm4(ah,     aS + acol);
            ldsm4(ah + 4, aS + 2048 + acol);
            ldsm4(bb,     bS + bcol);
            ldsm4(bb + 4, bS + 2048 + bcol);
#pragma unroll
            for (int mt = 0; mt < 2; ++mt)
#pragma unroll
                for (int nt = 0; nt < 4; ++nt)
                    mma8(acc[mt][nt], ah + 4 * mt, bb[2 * nt], bb[2 * nt + 1]);

            ldsm4(al,     aS + (A_LO - A_HI) + acol);
            ldsm4(al + 4, aS + (A_LO - A_HI) + 2048 + acol);
#pragma unroll
            for (int mt = 0; mt < 2; ++mt)
#pragma unroll
                for (int nt = 0; nt < 4; ++nt)
                    mma8(acc[mt][nt], al + 4 * mt, bb[2 * nt], bb[2 * nt + 1]);

            ldsm4(bb,     bS + (B_LO - B_HI) + bcol);
            ldsm4(bb + 4, bS + (B_LO - B_HI) + 2048 + bcol);
#pragma unroll
            for (int mt = 0; mt < 2; ++mt)
#pragma unroll
                for (int nt = 0; nt < 4; ++nt)
                    mma8(acc[mt][nt], ah + 4 * mt, bb[2 * nt], bb[2 * nt + 1]);
        }

        __syncthreads();

        if (c + 2 < NCH) {
            char* st = smem + (c & 1) * STAGE_BYTES;
#pragma unroll
            for (int it = 0; it < 4; ++it) {
                uint4 h, l; split4(pa[it], h, l);
                *reinterpret_cast<uint4*>(st + A_HI + offA[it]) = h;
                *reinterpret_cast<uint4*>(st + A_LO + offA[it]) = l;
            }
#pragma unroll
            for (int it = 0; it < 2; ++it) {
                uint4 h, l; split4(pb[it], h, l);
                *reinterpret_cast<uint4*>(st + B_HI + offB[it]) = h;
                *reinterpret_cast<uint4*>(st + B_LO + offB[it]) = l;
            }
            if (c + 3 < NCH) {
                const int k0 = (c + 3) * KC;
#pragma unroll
                for (int it = 0; it < 4; ++it)
                    pa[it] = *reinterpret_cast<const float4*>(Ap + (size_t)it * 32 * DD + k0);
#pragma unroll
                for (int it = 0; it < 2; ++it)
                    pb[it] = *reinterpret_cast<const float4*>(Wp + (size_t)it * 32 * DD + k0);
            }
        }
    }

    // logits -> smem (stride 65)
    float* lg = reinterpret_cast<float*>(smem);
    {
        const int r    = lane >> 2;
        const int ccol = (lane & 3) * 2;
#pragma unroll
        for (int mt = 0; mt < 2; ++mt) {
#pragma unroll
            for (int nt = 0; nt < 4; ++nt) {
                const int trow = wm * 32 + mt * 16 + r;
                const int e0   = wn * 32 + nt * 8 + ccol;
                float* p0 = lg + trow * 65 + e0;
                p0[0] = acc[mt][nt][0];
                p0[1] = acc[mt][nt][1];
                float* p1 = lg + (trow + 8) * 65 + e0;
                p1[0] = acc[mt][nt][2];
                p1[1] = acc[mt][nt][3];
            }
        }
    }
    __syncthreads();

    if (tid < TM) {
        float* row = lg + tid * 65;
        float mx = -3.4e38f;
        for (int e = 0; e < NE; ++e) {
            const float v = fmaf(row[e], s_cal[e], s_bias[e]);
            row[e] = v;
            mx = fmaxf(mx, v);
        }
        float sum = 0.f;
        for (int e = 0; e < NE; ++e) { const float p = expf(row[e] - mx); row[e] = p; sum += p; }
        const float inv = 1.f / sum;
        for (int e = 0; e < NE; ++e) row[e] *= inv;
    }
    __syncthreads();

    {
        float* dst = out_probs + (size_t)m0 * NE;
        for (int idx = tid; idx < TM * NE; idx += NT)
            dst[idx] = lg[(idx >> 6) * 65 + (idx & 63)];
    }
}

// Kernel2: exact sequential-k re-rank of top-12 candidates for ALL tokens.
// block = 256 thr, 64 tokens. smem: sA[64][132], sW[64][132], sP[64][65],
// cand[64][12], pv[64][12], dv[768].
#define FSM_BYTES ((2 * FT * FSTR + FT * 65 + FT * NCAND * 2 + FT * NCAND) * 4)

extern "C" __global__ void __launch_bounds__(FNT, 1)
router_fixup(const float* __restrict__ A, const float* __restrict__ W,
             const float* __restrict__ cal_s, const float* __restrict__ cal_b,
             const float* __restrict__ probs,
             float* __restrict__ out_w, float* __restrict__ out_i)
{
    extern __shared__ __align__(16) float fs[];
    float* sA   = fs;                           // 64*132
    float* sW   = sA + FT * FSTR;               // 64*132
    float* sP   = sW + FT * FSTR;               // 64*65
    int*   cand = (int*)(sP + FT * 65);         // 64*12
    float* pv   = (float*)(cand + FT * NCAND);  // 64*12
    float* dv   = pv + FT * NCAND;              // 768

    const int tid = threadIdx.x;
    const int t0  = blockIdx.x * FT;

    // load probs rows
    for (int i = tid; i < FT * NE; i += FNT)
        sP[(i >> 6) * 65 + (i & 63)] = probs[(size_t)(t0 + (i >> 6)) * NE + (i & 63)];
    __syncthreads();

    // top-12 candidates per token (by MMA probs; strict > => lowest index on tie)
    if (tid < FT) {
        float* row = sP + tid * 65;
        for (int kk = 0; kk < NCAND; ++kk) {
            float best = -1.f; int bi = 0;
            for (int e = 0; e < NE; ++e)
                if (row[e] > best) { best = row[e]; bi = e; }
            cand[tid * NCAND + kk] = bi;
            pv[tid * NCAND + kk]   = best;
            row[bi] = -1.f;
        }
    }
    __syncthreads();

    // dot assignments: d = tid + j*256 -> (token row r = d/12, cand slot c = d%12)
    int rr[3], ce[3];
#pragma unroll
    for (int j = 0; j < 3; ++j) {
        const int d = tid + j * FNT;
        rr[j] = d / NCAND;
        ce[j] = cand[rr[j] * NCAND + (d - rr[j] * NCAND)];
    }

    float acc[3] = {0.f, 0.f, 0.f};
    const int lr = tid >> 2;          // row 0..63
    const int lq = (tid & 3) * 8;     // f4 group start

    // prefetch tile 0
    float4 raf[8], rwf[8];
#pragma unroll
    for (int j = 0; j < 8; ++j) {
        raf[j] = *reinterpret_cast<const float4*>(A + (size_t)(t0 + lr) * DD + (lq + j) * 4);
        rwf[j] = *reinterpret_cast<const float4*>(W + (size_t)lr * DD + (lq + j) * 4);
    }

#pragma unroll 1
    for (int kt = 0; kt < DD / FKT; ++kt) {
#pragma unroll
        for (int j = 0; j < 8; ++j) {
            *reinterpret_cast<float4*>(sA + lr * FSTR + (lq + j) * 4) = raf[j];
            *reinterpret_cast<float4*>(sW + lr * FSTR + (lq + j) * 4) = rwf[j];
        }
        __syncthreads();

        if (kt + 1 < DD / FKT) {
            const int k0 = (kt + 1) * FKT;
#pragma unroll
            for (int j = 0; j < 8; ++j) {
                raf[j] = *reinterpret_cast<const float4*>(A + (size_t)(t0 + lr) * DD + k0 + (lq + j) * 4);
                rwf[j] = *reinterpret_cast<const float4*>(W + (size_t)lr * DD + k0 + (lq + j) * 4);
            }
        }

        // sequential ascending-k chain per dot (order matches reference GEMM)
#pragma unroll
        for (int j = 0; j < 3; ++j) {
            const float4* pA = reinterpret_cast<const float4*>(sA + rr[j] * FSTR);
            const float4* pW = reinterpret_cast<const float4*>(sW + ce[j] * FSTR);
            float a = acc[j];
#pragma unroll
            for (int q = 0; q < FKT / 4; ++q) {
                const float4 av = pA[q], wv = pW[q];
                a = fmaf(av.x, wv.x, a);
                a = fmaf(av.y, wv.y, a);
                a = fmaf(av.z, wv.z, a);
                a = fmaf(av.w, wv.w, a);
            }
            acc[j] = a;
        }
        __syncthreads();
    }

#pragma unroll
    for (int j = 0; j < 3; ++j) dv[tid + j * FNT] = acc[j];
    __syncthreads();

    // final exact re-rank + output
    if (tid < FT) {
        const size_t token = (size_t)t0 + tid;
        float le[NCAND], pw[NCAND];
        int   ei[NCAND];
        bool  used[NCAND];
#pragma unroll
        for (int c = 0; c < NCAND; ++c) {
            ei[c] = cand[tid * NCAND + c];
            le[c] = fmaf(dv[tid * NCAND + c], cal_s[ei[c]], cal_b[ei[c]]);
            pw[c] = pv[tid * NCAND + c];
            used[c] = false;
        }
        for (int kk = 0; kk < TOPK; ++kk) {
            float best = -3.4e38f; int bs = 0, bidx = 1 << 30;
            for (int c = 0; c < NCAND; ++c) {
                if (used[c]) continue;
                if (le[c] > best || (le[c] == best && ei[c] < bidx)) {
                    best = le[c]; bs = c; bidx = ei[c];
                }
            }
            used[bs] = true;
            out_w[token * TOPK + kk] = pw[bs];
            out_i[token * TOPK + kk] = (float)ei[bs];
        }
    }
}

extern "C" void kernel_launch(void* const* d_in, const int* in_sizes, int n_in,
                              void* d_out, int out_size)
{
    const float* h  = (const float*)d_in[0];
    const float* W  = (const float*)d_in[1];
    const float* sc = (const float*)d_in[2];
    const float* bi = (const float*)d_in[3];

    const int E = in_sizes[2];            // 64
    const int D = in_sizes[1] / E;        // 2048
    const int T = in_sizes[0] / D;        // 16384

    float* probs = (float*)d_out;
    float* wts   = probs + (size_t)T * E;
    float* idxf  = wts   + (size_t)T * TOPK;

    cudaFuncSetAttribute(router_mma, cudaFuncAttributeMaxDynamicSharedMemorySize, SMEM_TOTAL);
    cudaFuncSetAttribute(router_fixup, cudaFuncAttributeMaxDynamicSharedMemorySize, FSM_BYTES);
    router_mma<<<T / TM, NT, SMEM_TOTAL>>>(h, W, sc, bi, probs);
    router_fixup<<<T / FT, FNT, FSM_BYTES>>>(h, W, sc, bi, probs, wts, idxf);
}

// round 10
// speedup vs baseline: 1.3356x; 1.3356x over previous
#include <cuda_runtime.h>
#include <cstdint>
#include <math.h>

// Router: probs = softmax(calib(H @ W^T)), top-8.
// Kernel1 (unchanged from R9, proven): mma.sync tf32 3x split -> probs.
// Kernel2 (restructured): one thread per token; exact sequential ascending-k
// fp32 recompute of its 12 candidate logits (A value loaded once per k for all
// 12 cands), re-rank top-8. Same accumulation order as R9 (proven exact).
// Output packing: d_out = probs[T*64] || topk_w[T*8] || topk_idx(as float)[T*8]

#define TM   128
#define NE   64
#define DD   2048
#define KC   32
#define NCH  (DD / KC)
#define NT   256
#define TOPK 8

#define STAGE_BYTES 49152
#define A_HI 0
#define A_LO 16384
#define B_HI 32768
#define B_LO 40960
#define SM_CAL  (2 * STAGE_BYTES)
#define SM_BIAS (SM_CAL + 256)
#define SMEM_TOTAL (SM_CAL + 512)

// fixup v2 config
#define FT2   64          // tokens per block == threads per block
#define FNT2  64
#define FKT2  128         // k tile
#define NC    12          // candidates
#define SWP   33          // row stride in float4 units (odd -> conflict-free A)
#define FSM2  (2 * 64 * SWP * 16)   // sA4[64*33] + sW4[64*33] float4s = 67584 B

static __device__ __forceinline__ uint32_t smem_u32(const void* p) {
    uint32_t a;
    asm("{ .reg .u64 t; cvta.to.shared.u64 t, %1; cvt.u32.u64 %0, t; }" : "=r"(a) : "l"(p));
    return a;
}
static __device__ __forceinline__ uint32_t f2tf(float x) {
    uint32_t r; asm("cvt.rna.tf32.f32 %0, %1;" : "=r"(r) : "f"(x)); return r;
}
static __device__ __forceinline__ void split4(float4 v, uint4& h, uint4& l) {
    h.x = f2tf(v.x); l.x = f2tf(v.x - __uint_as_float(h.x));
    h.y = f2tf(v.y); l.y = f2tf(v.y - __uint_as_float(h.y));
    h.z = f2tf(v.z); l.z = f2tf(v.z - __uint_as_float(h.z));
    h.w = f2tf(v.w); l.w = f2tf(v.w - __uint_as_float(h.w));
}
static __device__ __forceinline__ void ldsm4(uint32_t* r, uint32_t addr) {
    asm volatile("ldmatrix.sync.aligned.m8n8.x4.shared.b16 {%0,%1,%2,%3}, [%4];"
        : "=r"(r[0]), "=r"(r[1]), "=r"(r[2]), "=r"(r[3]) : "r"(addr));
}
static __device__ __forceinline__ void mma8(float* c, const uint32_t* a,
                                            uint32_t b0, uint32_t b1) {
    asm volatile("mma.sync.aligned.m16n8k8.row.col.f32.tf32.tf32.f32 "
        "{%0,%1,%2,%3}, {%4,%5,%6,%7}, {%8,%9}, {%0,%1,%2,%3};"
        : "+f"(c[0]), "+f"(c[1]), "+f"(c[2]), "+f"(c[3])
        : "r"(a[0]), "r"(a[1]), "r"(a[2]), "r"(a[3]), "r"(b0), "r"(b1));
}

extern "C" __global__ void __launch_bounds__(NT, 1)
router_mma(const float* __restrict__ A, const float* __restrict__ W,
           const float* __restrict__ cal_s, const float* __restrict__ cal_b,
           float* __restrict__ out_probs)
{
    extern __shared__ __align__(16) char smem[];
    const uint32_t sbase = smem_u32(smem);
    const int tid  = threadIdx.x;
    const int lane = tid & 31;
    const int w    = tid >> 5;
    const int wm   = w >> 1;
    const int wn   = w & 1;
    const int m0   = blockIdx.x * TM;

    float* s_cal  = reinterpret_cast<float*>(smem + SM_CAL);
    float* s_bias = reinterpret_cast<float*>(smem + SM_BIAS);
    if (tid < NE) { s_cal[tid] = cal_s[tid]; s_bias[tid] = cal_b[tid]; }

    const int ra = tid >> 3;
    const int c4 = tid & 7;
    uint32_t offA[4], offB[2];
#pragma unroll
    for (int it = 0; it < 4; ++it) {
        const int t = ra + it * 32;
        offA[it] = (uint32_t)t * 128 + (uint32_t)((c4 ^ (t & 7)) << 4);
    }
#pragma unroll
    for (int it = 0; it < 2; ++it) {
        const int t = ra + it * 32;
        offB[it] = (uint32_t)t * 128 + (uint32_t)((c4 ^ (t & 7)) << 4);
    }
    const float* Ap = A + (size_t)(m0 + ra) * DD + c4 * 4;
    const float* Wp = W + (size_t)ra * DD + c4 * 4;

#pragma unroll
    for (int cc = 0; cc < 2; ++cc) {
        char* st = smem + cc * STAGE_BYTES;
        const int k0 = cc * KC;
#pragma unroll
        for (int it = 0; it < 4; ++it) {
            float4 v = *reinterpret_cast<const float4*>(Ap + (size_t)it * 32 * DD + k0);
            uint4 h, l; split4(v, h, l);
            *reinterpret_cast<uint4*>(st + A_HI + offA[it]) = h;
            *reinterpret_cast<uint4*>(st + A_LO + offA[it]) = l;
        }
#pragma unroll
        for (int it = 0; it < 2; ++it) {
            float4 v = *reinterpret_cast<const float4*>(Wp + (size_t)it * 32 * DD + k0);
            uint4 h, l; split4(v, h, l);
            *reinterpret_cast<uint4*>(st + B_HI + offB[it]) = h;
            *reinterpret_cast<uint4*>(st + B_LO + offB[it]) = l;
        }
    }
    __syncthreads();

    float4 pa[4], pb[2];
    {
        const int k0 = 2 * KC;
#pragma unroll
        for (int it = 0; it < 4; ++it)
            pa[it] = *reinterpret_cast<const float4*>(Ap + (size_t)it * 32 * DD + k0);
#pragma unroll
        for (int it = 0; it < 2; ++it)
            pb[it] = *reinterpret_cast<const float4*>(Wp + (size_t)it * 32 * DD + k0);
    }

    const int arow = wm * 32 + (lane & 15);
    const int acs  = lane >> 4;
    const int ax   = arow & 7;
    const uint32_t abase0 = sbase + A_HI + (uint32_t)arow * 128;
    const int g    = lane >> 3;
    const int brow = wn * 32 + ((g >> 1) << 3) + (lane & 7);
    const int bcs  = g & 1;
    const int bx   = brow & 7;
    const uint32_t bbase0 = sbase + B_HI + (uint32_t)brow * 128;

    float acc[2][4][4];
#pragma unroll
    for (int mt = 0; mt < 2; ++mt)
#pragma unroll
        for (int nt = 0; nt < 4; ++nt)
#pragma unroll
            for (int q = 0; q < 4; ++q) acc[mt][nt][q] = 0.f;

#pragma unroll 1
    for (int c = 0; c < NCH; ++c) {
        const uint32_t stoff = (uint32_t)(c & 1) * STAGE_BYTES;
        const uint32_t aS = abase0 + stoff;
        const uint32_t bS = bbase0 + stoff;

#pragma unroll
        for (int s8 = 0; s8 < 4; ++s8) {
            uint32_t ah[8], al[8], bb[8];
            const uint32_t acol = (uint32_t)(((2 * s8 + acs) ^ ax) << 4);
            const uint32_t bcol = (uint32_t)(((2 * s8 + bcs) ^ bx) << 4);

            ldsm4(ah,     aS + acol);
            ldsm4(ah + 4, aS + 2048 + acol);
            ldsm4(bb,     bS + bcol);
            ldsm4(bb + 4, bS + 2048 + bcol);
#pragma unroll
            for (int mt = 0; mt < 2; ++mt)
#pragma unroll
                for (int nt = 0; nt < 4; ++nt)
                    mma8(acc[mt][nt], ah + 4 * mt, bb[2 * nt], bb[2 * nt + 1]);

            ldsm4(al,     aS + (A_LO - A_HI) + acol);
            ldsm4(al + 4, aS + (A_LO - A_HI) + 2048 + acol);
#pragma unroll
            for (int mt = 0; mt < 2; ++mt)
#pragma unroll
                for (int nt = 0; nt < 4; ++nt)
                    mma8(acc[mt][nt], al + 4 * mt, bb[2 * nt], bb[2 * nt + 1]);

            ldsm4(bb,     bS + (B_LO - B_HI) + bcol);
            ldsm4(bb + 4, bS + (B_LO - B_HI) + 2048 + bcol);
#pragma unroll
            for (int mt = 0; mt < 2; ++mt)
#pragma unroll
                for (int nt = 0; nt < 4; ++nt)
                    mma8(acc[mt][nt], ah + 4 * mt, bb[2 * nt], bb[2 * nt + 1]);
        }

        __syncthreads();

        if (c + 2 < NCH) {
            char* st = smem + (c & 1) * STAGE_BYTES;
#pragma unroll
            for (int it = 0; it < 4; ++it) {
                uint4 h, l; split4(pa[it], h, l);
                *reinterpret_cast<uint4*>(st + A_HI + offA[it]) = h;
                *reinterpret_cast<uint4*>(st + A_LO + offA[it]) = l;
            }
#pragma unroll
            for (int it = 0; it < 2; ++it) {
                uint4 h, l; split4(pb[it], h, l);
                *reinterpret_cast<uint4*>(st + B_HI + offB[it]) = h;
                *reinterpret_cast<uint4*>(st + B_LO + offB[it]) = l;
            }
            if (c + 3 < NCH) {
                const int k0 = (c + 3) * KC;
#pragma unroll
                for (int it = 0; it < 4; ++it)
                    pa[it] = *reinterpret_cast<const float4*>(Ap + (size_t)it * 32 * DD + k0);
#pragma unroll
                for (int it = 0; it < 2; ++it)
                    pb[it] = *reinterpret_cast<const float4*>(Wp + (size_t)it * 32 * DD + k0);
            }
        }
    }

    float* lg = reinterpret_cast<float*>(smem);
    {
        const int r    = lane >> 2;
        const int ccol = (lane & 3) * 2;
#pragma unroll
        for (int mt = 0; mt < 2; ++mt) {
#pragma unroll
            for (int nt = 0; nt < 4; ++nt) {
                const int trow = wm * 32 + mt * 16 + r;
                const int e0   = wn * 32 + nt * 8 + ccol;
                float* p0 = lg + trow * 65 + e0;
                p0[0] = acc[mt][nt][0];
                p0[1] = acc[mt][nt][1];
                float* p1 = lg + (trow + 8) * 65 + e0;
                p1[0] = acc[mt][nt][2];
                p1[1] = acc[mt][nt][3];
            }
        }
    }
    __syncthreads();

    if (tid < TM) {
        float* row = lg + tid * 65;
        float mx = -3.4e38f;
        for (int e = 0; e < NE; ++e) {
            const float v = fmaf(row[e], s_cal[e], s_bias[e]);
            row[e] = v;
            mx = fmaxf(mx, v);
        }
        float sum = 0.f;
        for (int e = 0; e < NE; ++e) { const float p = expf(row[e] - mx); row[e] = p; sum += p; }
        const float inv = 1.f / sum;
        for (int e = 0; e < NE; ++e) row[e] *= inv;
    }
    __syncthreads();

    {
        float* dst = out_probs + (size_t)m0 * NE;
        for (int idx = tid; idx < TM * NE; idx += NT)
            dst[idx] = lg[(idx >> 6) * 65 + (idx & 63)];
    }
}

// ---------------- fixup v2: one thread per token ----------------
extern "C" __global__ void __launch_bounds__(FNT2)
router_fixup(const float* __restrict__ A, const float* __restrict__ W,
             const float* __restrict__ cal_s, const float* __restrict__ cal_b,
             const float* __restrict__ probs,
             float* __restrict__ out_w, float* __restrict__ out_i)
{
    extern __shared__ __align__(16) float4 fsm[];
    float4* sA4 = fsm;                 // [64][SWP]
    float4* sW4 = fsm + 64 * SWP;      // [64][SWP]
    float*  sP  = reinterpret_cast<float*>(fsm);  // probs staging (stride 65), overwritten later

    const int tid = threadIdx.x;
    const int t0  = blockIdx.x * FT2;

    // stage probs rows (coalesced)
    for (int i = tid; i < FT2 * NE; i += FNT2)
        sP[(i >> 6) * 65 + (i & 63)] = probs[(size_t)(t0 + (i >> 6)) * NE + (i & 63)];
    __syncthreads();

    // per-thread top-12 candidate selection (strict > => lowest index on tie)
    int   cand[NC];
    float pw[NC];
    {
        float* row = sP + tid * 65;
        for (int kk = 0; kk < NC; ++kk) {
            float best = -1.f; int bi = 0;
            for (int e = 0; e < NE; ++e)
                if (row[e] > best) { best = row[e]; bi = e; }
            cand[kk] = bi;
            pw[kk]   = best;
            row[bi]  = -1.f;
        }
    }
    __syncthreads();   // selection done before sA4 overwrites the probs area

    float acc[NC];
#pragma unroll
    for (int j = 0; j < NC; ++j) acc[j] = 0.f;

#pragma unroll 1
    for (int kt = 0; kt < DD / FKT2; ++kt) {
        // stage A tile [64 tok][128 k] (coalesced LDG, conflict-free STS.128)
#pragma unroll
        for (int it = 0; it < 32; ++it) {
            const int f = tid + it * FNT2;
            const int row = f >> 5, cc = f & 31;
            sA4[row * SWP + cc] =
                *reinterpret_cast<const float4*>(A + (size_t)(t0 + row) * DD + kt * FKT2 + cc * 4);
        }
        // stage W tile [64 exp][128 k]
#pragma unroll
        for (int it = 0; it < 32; ++it) {
            const int f = tid + it * FNT2;
            const int row = f >> 5, cc = f & 31;
            sW4[row * SWP + cc] =
                *reinterpret_cast<const float4*>(W + (size_t)row * DD + kt * FKT2 + cc * 4);
        }
        __syncthreads();

        // exact ascending-k chains: A value loaded once, 12 cands share it
        const float4* aRow = sA4 + tid * SWP;
#pragma unroll 4
        for (int q4 = 0; q4 < FKT2 / 4; ++q4) {
            const float4 a4 = aRow[q4];
#pragma unroll
            for (int j = 0; j < NC; ++j) {
                const float4 w4 = sW4[cand[j] * SWP + q4];
                float a = acc[j];
                a = fmaf(a4.x, w4.x, a);
                a = fmaf(a4.y, w4.y, a);
                a = fmaf(a4.z, w4.z, a);
                a = fmaf(a4.w, w4.w, a);
                acc[j] = a;
            }
        }
        __syncthreads();
    }

    // exact re-rank + output
    {
        const size_t token = (size_t)t0 + tid;
        float le[NC];
        bool  used[NC];
#pragma unroll
        for (int j = 0; j < NC; ++j) {
            le[j] = fmaf(acc[j], cal_s[cand[j]], cal_b[cand[j]]);
            used[j] = false;
        }
        for (int kk = 0; kk < TOPK; ++kk) {
            float best = -3.4e38f; int bs = 0, bidx = 1 << 30;
#pragma unroll
            for (int j = 0; j < NC; ++j) {
                if (used[j]) continue;
                if (le[j] > best || (le[j] == best && cand[j] < bidx)) {
                    best = le[j]; bs = j; bidx = cand[j];
                }
            }
            used[bs] = true;
            out_w[token * TOPK + kk] = pw[bs];
            out_i[token * TOPK + kk] = (float)cand[bs];
        }
    }
}

extern "C" void kernel_launch(void* const* d_in, const int* in_sizes, int n_in,
                              void* d_out, int out_size)
{
    const float* h  = (const float*)d_in[0];
    const float* W  = (const float*)d_in[1];
    const float* sc = (const float*)d_in[2];
    const float* bi = (const float*)d_in[3];

    const int E = in_sizes[2];            // 64
    const int D = in_sizes[1] / E;        // 2048
    const int T = in_sizes[0] / D;        // 16384

    float* probs = (float*)d_out;
    float* wts   = probs + (size_t)T * E;
    float* idxf  = wts   + (size_t)T * TOPK;

    cudaFuncSetAttribute(router_mma, cudaFuncAttributeMaxDynamicSharedMemorySize, SMEM_TOTAL);
    cudaFuncSetAttribute(router_fixup, cudaFuncAttributeMaxDynamicSharedMemorySize, FSM2);
    router_mma<<<T / TM, NT, SMEM_TOTAL>>>(h, W, sc, bi, probs);
    router_fixup<<<T / FT2, FNT2, FSM2>>>(h, W, sc, bi, probs, wts, idxf);
}

// round 11
// speedup vs baseline: 1.3951x; 1.0446x over previous
#include <cuda_runtime.h>
#include <cstdint>
#include <math.h>

// Router: probs = softmax(calib(H @ W^T)), top-8.
// Kernel1 (unchanged, proven): mma.sync tf32 3x split -> probs.
// Kernel2 v3: 4 threads/token x 3 candidates; exact ascending-k fp32 chains
// (same order as R10, proven) ONLY for tokens whose top-9 MMA prob gaps are
// < 5e-4 (MMA prob error <= ~3e-6 -> gap>5e-4 proves MMA ranking correct).
// Output packing: d_out = probs[T*64] || topk_w[T*8] || topk_idx(as float)[T*8]

#define TM   128
#define NE   64
#define DD   2048
#define KC   32
#define NCH  (DD / KC)
#define NT   256
#define TOPK 8

#define STAGE_BYTES 49152
#define A_HI 0
#define A_LO 16384
#define B_HI 32768
#define B_LO 40960
#define SM_CAL  (2 * STAGE_BYTES)
#define SM_BIAS (SM_CAL + 256)
#define SMEM_TOTAL (SM_CAL + 512)

// fixup v3 config
#define FT3   64            // tokens per block
#define FNT3  256           // threads (4 per token)
#define NC    12            // candidates per token
#define SWP   33            // row stride in float4 units
#define GAPE  5e-4f         // prob-gap safety threshold (~150x MMA prob noise)

static __device__ __forceinline__ uint32_t smem_u32(const void* p) {
    uint32_t a;
    asm("{ .reg .u64 t; cvta.to.shared.u64 t, %1; cvt.u32.u64 %0, t; }" : "=r"(a) : "l"(p));
    return a;
}
static __device__ __forceinline__ uint32_t f2tf(float x) {
    uint32_t r; asm("cvt.rna.tf32.f32 %0, %1;" : "=r"(r) : "f"(x)); return r;
}
static __device__ __forceinline__ void split4(float4 v, uint4& h, uint4& l) {
    h.x = f2tf(v.x); l.x = f2tf(v.x - __uint_as_float(h.x));
    h.y = f2tf(v.y); l.y = f2tf(v.y - __uint_as_float(h.y));
    h.z = f2tf(v.z); l.z = f2tf(v.z - __uint_as_float(h.z));
    h.w = f2tf(v.w); l.w = f2tf(v.w - __uint_as_float(h.w));
}
static __device__ __forceinline__ void ldsm4(uint32_t* r, uint32_t addr) {
    asm volatile("ldmatrix.sync.aligned.m8n8.x4.shared.b16 {%0,%1,%2,%3}, [%4];"
        : "=r"(r[0]), "=r"(r[1]), "=r"(r[2]), "=r"(r[3]) : "r"(addr));
}
static __device__ __forceinline__ void mma8(float* c, const uint32_t* a,
                                            uint32_t b0, uint32_t b1) {
    asm volatile("mma.sync.aligned.m16n8k8.row.col.f32.tf32.tf32.f32 "
        "{%0,%1,%2,%3}, {%4,%5,%6,%7}, {%8,%9}, {%0,%1,%2,%3};"
        : "+f"(c[0]), "+f"(c[1]), "+f"(c[2]), "+f"(c[3])
        : "r"(a[0]), "r"(a[1]), "r"(a[2]), "r"(a[3]), "r"(b0), "r"(b1));
}

extern "C" __global__ void __launch_bounds__(NT, 1)
router_mma(const float* __restrict__ A, const float* __restrict__ W,
           const float* __restrict__ cal_s, const float* __restrict__ cal_b,
           float* __restrict__ out_probs)
{
    extern __shared__ __align__(16) char smem[];
    const uint32_t sbase = smem_u32(smem);
    const int tid  = threadIdx.x;
    const int lane = tid & 31;
    const int w    = tid >> 5;
    const int wm   = w >> 1;
    const int wn   = w & 1;
    const int m0   = blockIdx.x * TM;

    float* s_cal  = reinterpret_cast<float*>(smem + SM_CAL);
    float* s_bias = reinterpret_cast<float*>(smem + SM_BIAS);
    if (tid < NE) { s_cal[tid] = cal_s[tid]; s_bias[tid] = cal_b[tid]; }

    const int ra = tid >> 3;
    const int c4 = tid & 7;
    uint32_t offA[4], offB[2];
#pragma unroll
    for (int it = 0; it < 4; ++it) {
        const int t = ra + it * 32;
        offA[it] = (uint32_t)t * 128 + (uint32_t)((c4 ^ (t & 7)) << 4);
    }
#pragma unroll
    for (int it = 0; it < 2; ++it) {
        const int t = ra + it * 32;
        offB[it] = (uint32_t)t * 128 + (uint32_t)((c4 ^ (t & 7)) << 4);
    }
    const float* Ap = A + (size_t)(m0 + ra) * DD + c4 * 4;
    const float* Wp = W + (size_t)ra * DD + c4 * 4;

#pragma unroll
    for (int cc = 0; cc < 2; ++cc) {
        char* st = smem + cc * STAGE_BYTES;
        const int k0 = cc * KC;
#pragma unroll
        for (int it = 0; it < 4; ++it) {
            float4 v = *reinterpret_cast<const float4*>(Ap + (size_t)it * 32 * DD + k0);
            uint4 h, l; split4(v, h, l);
            *reinterpret_cast<uint4*>(st + A_HI + offA[it]) = h;
            *reinterpret_cast<uint4*>(st + A_LO + offA[it]) = l;
        }
#pragma unroll
        for (int it = 0; it < 2; ++it) {
            float4 v = *reinterpret_cast<const float4*>(Wp + (size_t)it * 32 * DD + k0);
            uint4 h, l; split4(v, h, l);
            *reinterpret_cast<uint4*>(st + B_HI + offB[it]) = h;
            *reinterpret_cast<uint4*>(st + B_LO + offB[it]) = l;
        }
    }
    __syncthreads();

    float4 pa[4], pb[2];
    {
        const int k0 = 2 * KC;
#pragma unroll
        for (int it = 0; it < 4; ++it)
            pa[it] = *reinterpret_cast<const float4*>(Ap + (size_t)it * 32 * DD + k0);
#pragma unroll
        for (int it = 0; it < 2; ++it)
            pb[it] = *reinterpret_cast<const float4*>(Wp + (size_t)it * 32 * DD + k0);
    }

    const int arow = wm * 32 + (lane & 15);
    const int acs  = lane >> 4;
    const int ax   = arow & 7;
    const uint32_t abase0 = sbase + A_HI + (uint32_t)arow * 128;
    const int g    = lane >> 3;
    const int brow = wn * 32 + ((g >> 1) << 3) + (lane & 7);
    const int bcs  = g & 1;
    const int bx   = brow & 7;
    const uint32_t bbase0 = sbase + B_HI + (uint32_t)brow * 128;

    float acc[2][4][4];
#pragma unroll
    for (int mt = 0; mt < 2; ++mt)
#pragma unroll
        for (int nt = 0; nt < 4; ++nt)
#pragma unroll
            for (int q = 0; q < 4; ++q) acc[mt][nt][q] = 0.f;

#pragma unroll 1
    for (int c = 0; c < NCH; ++c) {
        const uint32_t stoff = (uint32_t)(c & 1) * STAGE_BYTES;
        const uint32_t aS = abase0 + stoff;
        const uint32_t bS = bbase0 + stoff;

#pragma unroll
        for (int s8 = 0; s8 < 4; ++s8) {
            uint32_t ah[8], al[8], bb[8];
            const uint32_t acol = (uint32_t)(((2 * s8 + acs) ^ ax) << 4);
            const uint32_t bcol = (uint32_t)(((2 * s8 + bcs) ^ bx) << 4);

            ldsm4(ah,     aS + acol);
            ldsm4(ah + 4, aS + 2048 + acol);
            ldsm4(bb,     bS + bcol);
            ldsm4(bb + 4, bS + 2048 + bcol);
#pragma unroll
            for (int mt = 0; mt < 2; ++mt)
#pragma unroll
                for (int nt = 0; nt < 4; ++nt)
                    mma8(acc[mt][nt], ah + 4 * mt, bb[2 * nt], bb[2 * nt + 1]);

            ldsm4(al,     aS + (A_LO - A_HI) + acol);
            ldsm4(al + 4, aS + (A_LO - A_HI) + 2048 + acol);
#pragma unroll
            for (int mt = 0; mt < 2; ++mt)
#pragma unroll
                for (int nt = 0; nt < 4; ++nt)
                    mma8(acc[mt][nt], al + 4 * mt, bb[2 * nt], bb[2 * nt + 1]);

            ldsm4(bb,     bS + (B_LO - B_HI) + bcol);
            ldsm4(bb + 4, bS + (B_LO - B_HI) + 2048 + bcol);
#pragma unroll
            for (int mt = 0; mt < 2; ++mt)
#pragma unroll
                for (int nt = 0; nt < 4; ++nt)
                    mma8(acc[mt][nt], ah + 4 * mt, bb[2 * nt], bb[2 * nt + 1]);
        }

        __syncthreads();

        if (c + 2 < NCH) {
            char* st = smem + (c & 1) * STAGE_BYTES;
#pragma unroll
            for (int it = 0; it < 4; ++it) {
                uint4 h, l; split4(pa[it], h, l);
                *reinterpret_cast<uint4*>(st + A_HI + offA[it]) = h;
                *reinterpret_cast<uint4*>(st + A_LO + offA[it]) = l;
            }
#pragma unroll
            for (int it = 0; it < 2; ++it) {
                uint4 h, l; split4(pb[it], h, l);
                *reinterpret_cast<uint4*>(st + B_HI + offB[it]) = h;
                *reinterpret_cast<uint4*>(st + B_LO + offB[it]) = l;
            }
            if (c + 3 < NCH) {
                const int k0 = (c + 3) * KC;
#pragma unroll
                for (int it = 0; it < 4; ++it)
                    pa[it] = *reinterpret_cast<const float4*>(Ap + (size_t)it * 32 * DD + k0);
#pragma unroll
                for (int it = 0; it < 2; ++it)
                    pb[it] = *reinterpret_cast<const float4*>(Wp + (size_t)it * 32 * DD + k0);
            }
        }
    }

    float* lg = reinterpret_cast<float*>(smem);
    {
        const int r    = lane >> 2;
        const int ccol = (lane & 3) * 2;
#pragma unroll
        for (int mt = 0; mt < 2; ++mt) {
#pragma unroll
            for (int nt = 0; nt < 4; ++nt) {
                const int trow = wm * 32 + mt * 16 + r;
                const int e0   = wn * 32 + nt * 8 + ccol;
                float* p0 = lg + trow * 65 + e0;
                p0[0] = acc[mt][nt][0];
                p0[1] = acc[mt][nt][1];
                float* p1 = lg + (trow + 8) * 65 + e0;
                p1[0] = acc[mt][nt][2];
                p1[1] = acc[mt][nt][3];
            }
        }
    }
    __syncthreads();

    if (tid < TM) {
        float* row = lg + tid * 65;
        float mx = -3.4e38f;
        for (int e = 0; e < NE; ++e) {
            const float v = fmaf(row[e], s_cal[e], s_bias[e]);
            row[e] = v;
            mx = fmaxf(mx, v);
        }
        float sum = 0.f;
        for (int e = 0; e < NE; ++e) { const float p = expf(row[e] - mx); row[e] = p; sum += p; }
        const float inv = 1.f / sum;
        for (int e = 0; e < NE; ++e) row[e] *= inv;
    }
    __syncthreads();

    {
        float* dst = out_probs + (size_t)m0 * NE;
        for (int idx = tid; idx < TM * NE; idx += NT)
            dst[idx] = lg[(idx >> 6) * 65 + (idx & 63)];
    }
}

// ---------------- fixup v3 ----------------
// smem: sA4[64*33] f4 | sW4[64*33] f4 | cand[64*12] | pw[64*12] | le[64*12] | flag[64]
#define FX_A    0
#define FX_W    (64 * SWP)                       // f4 index
#define FX_EXT  (2 * 64 * SWP * 16)              // byte offset of extras
#define FSM3    (FX_EXT + (64 * NC * 4) * 3 + 256)

extern "C" __global__ void __launch_bounds__(FNT3, 1)
router_fixup(const float* __restrict__ A, const float* __restrict__ W,
             const float* __restrict__ cal_s, const float* __restrict__ cal_b,
             const float* __restrict__ probs,
             float* __restrict__ out_w, float* __restrict__ out_i)
{
    extern __shared__ __align__(16) char fsmem[];
    float4* sA4  = reinterpret_cast<float4*>(fsmem) + FX_A;
    float4* sW4  = reinterpret_cast<float4*>(fsmem) + FX_W;
    int*    sCand = reinterpret_cast<int*>(fsmem + FX_EXT);
    float*  sPw   = reinterpret_cast<float*>(fsmem + FX_EXT + 64 * NC * 4);
    float*  sLe   = reinterpret_cast<float*>(fsmem + FX_EXT + 2 * 64 * NC * 4);
    int*    sFlag = reinterpret_cast<int*>(fsmem + FX_EXT + 3 * 64 * NC * 4);
    float*  sP    = reinterpret_cast<float*>(sA4);   // probs staging (reused)

    const int tid = threadIdx.x;
    const int t0  = blockIdx.x * FT3;

    // stage probs (stride 65)
    for (int i = tid; i < FT3 * NE; i += FNT3)
        sP[(i >> 6) * 65 + (i & 63)] = probs[(size_t)(t0 + (i >> 6)) * NE + (i & 63)];
    __syncthreads();

    // selection + safety flag (one thread per token)
    if (tid < FT3) {
        float* row = sP + tid * 65;
        float prev = 2.f;
        bool flag = false;
        for (int kk = 0; kk < NC; ++kk) {
            float best = -1.f; int bi = 0;
            for (int e = 0; e < NE; ++e)
                if (row[e] > best) { best = row[e]; bi = e; }
            sCand[tid * NC + kk] = bi;
            sPw[tid * NC + kk]   = best;
            row[bi] = -1.f;
            if (kk >= 1 && kk <= 8 && (prev - best) < GAPE) flag = true;
            prev = best;
        }
        sFlag[tid] = flag ? 1 : 0;
    }
    __syncthreads();

    // per-thread candidate slots: token r, 3 cands
    const int r    = tid >> 2;
    const int s0   = (tid & 3) * 3;
    const int fl   = sFlag[r];
    int c[3], cx[3];
#pragma unroll
    for (int j = 0; j < 3; ++j) {
        c[j]  = sCand[r * NC + s0 + j];
        cx[j] = (c[j] >> 3) & 7;
    }
    float acc[3] = {0.f, 0.f, 0.f};
    __syncthreads();   // selection reads done before sA4 overwrite

#pragma unroll 1
    for (int kt = 0; kt < DD / 128; ++kt) {
        const int kb = kt * 32;    // f4 units
        // stage A (predicated on row flag)
#pragma unroll
        for (int it = 0; it < 8; ++it) {
            const int f = tid + it * FNT3;
            const int row = f >> 5, col = f & 31;
            if (sFlag[row])
                sA4[row * SWP + col] =
                    *reinterpret_cast<const float4*>(A + (size_t)(t0 + row) * DD + (kb + col) * 4);
        }
        // stage W with xor swizzle
#pragma unroll
        for (int it = 0; it < 8; ++it) {
            const int f = tid + it * FNT3;
            const int row = f >> 5, col = f & 31;
            sW4[row * SWP + (col ^ ((row >> 3) & 7))] =
                *reinterpret_cast<const float4*>(W + (size_t)row * DD + (kb + col) * 4);
        }
        __syncthreads();

        if (fl) {
            const float4* aRow = sA4 + r * SWP;
#pragma unroll 2
            for (int q4 = 0; q4 < 32; ++q4) {
                const float4 a4 = aRow[q4];
#pragma unroll
                for (int j = 0; j < 3; ++j) {
                    const float4 w4 = sW4[c[j] * SWP + (q4 ^ cx[j])];
                    float a = acc[j];
                    a = fmaf(a4.x, w4.x, a);
                    a = fmaf(a4.y, w4.y, a);
                    a = fmaf(a4.z, w4.z, a);
                    a = fmaf(a4.w, w4.w, a);
                    acc[j] = a;
                }
            }
        }
        __syncthreads();
    }

    // calibrated exact logits -> smem
    if (fl) {
#pragma unroll
        for (int j = 0; j < 3; ++j)
            sLe[r * NC + s0 + j] = fmaf(acc[j], cal_s[c[j]], cal_b[c[j]]);
    }
    __syncthreads();

    if (tid < FT3) {
        const size_t token = (size_t)t0 + tid;
        if (!sFlag[tid]) {
            // MMA ranking provably correct
#pragma unroll
            for (int kk = 0; kk < TOPK; ++kk) {
                out_w[token * TOPK + kk] = sPw[tid * NC + kk];
                out_i[token * TOPK + kk] = (float)sCand[tid * NC + kk];
            }
        } else {
            float le[NC], pwv[NC];
            int   ei[NC];
            bool  used[NC];
#pragma unroll
            for (int j = 0; j < NC; ++j) {
                le[j]  = sLe[tid * NC + j];
                pwv[j] = sPw[tid * NC + j];
                ei[j]  = sCand[tid * NC + j];
                used[j] = false;
            }
            for (int kk = 0; kk < TOPK; ++kk) {
                float best = -3.4e38f; int bs = 0, bidx = 1 << 30;
#pragma unroll
                for (int j = 0; j < NC; ++j) {
                    if (used[j]) continue;
                    if (le[j] > best || (le[j] == best && ei[j] < bidx)) {
                        best = le[j]; bs = j; bidx = ei[j];
                    }
                }
                used[bs] = true;
                out_w[token * TOPK + kk] = pwv[bs];
                out_i[token * TOPK + kk] = (float)ei[bs];
            }
        }
    }
}

extern "C" void kernel_launch(void* const* d_in, const int* in_sizes, int n_in,
                              void* d_out, int out_size)
{
    const float* h  = (const float*)d_in[0];
    const float* W  = (const float*)d_in[1];
    const float* sc = (const float*)d_in[2];
    const float* bi = (const float*)d_in[3];

    const int E = in_sizes[2];            // 64
    const int D = in_sizes[1] / E;        // 2048
    const int T = in_sizes[0] / D;        // 16384

    float* probs = (float*)d_out;
    float* wts   = probs + (size_t)T * E;
    float* idxf  = wts   + (size_t)T * TOPK;

    cudaFuncSetAttribute(router_mma, cudaFuncAttributeMaxDynamicSharedMemorySize, SMEM_TOTAL);
    cudaFuncSetAttribute(router_fixup, cudaFuncAttributeMaxDynamicSharedMemorySize, FSM3);
    router_mma<<<T / TM, NT, SMEM_TOTAL>>>(h, W, sc, bi, probs);
    router_fixup<<<T / FT3, FNT3, FSM3>>>(h, W, sc, bi, probs, wts, idxf);
}